// round 14
// baseline (speedup 1.0000x reference)
#include <cuda_runtime.h>
#include <cuda_fp16.h>
#include <stdint.h>
#include <math.h>

// ---------------------------------------------------------------------------
// B=16, D=8, S=256, L=512.
//   x [32768,512] f32 | Wqkv [1536,512] | bqkv [1536] | n (int)
// d_out: output [16,2048,512] (16,777,216 f32) then out_mat [16,2048,2048].
//
// All GEMMs: legacy mma.sync.m16n8k16 fp16, 2-way split precision (hi+lo,
// 3 HMMAs per logical MMA). Operands pre-split to half planes.
// 3-stage cp.async ring (constant stage offsets), loads issued mid-compute,
// XOR-swizzled 64B-row smem tiles, ldmatrix fragments. (R9 compute config.)
// R14: QKV split into QK-proj and V-proj; V-proj runs on a side stream
// concurrent with scores+softmax (fills their idle-SM tail waves).
// Off-diagonal zero-fill stays on a low-priority stream, joined at the end.
// ---------------------------------------------------------------------------

static __device__ __half g_xs [2][16777216];  // x split planes [32768*512]
static __device__ __half g_ws [2][786432];    // Wqkv split planes [1536*512]
static __device__ __half g_qks[2][33554432];  // Q|K split [32768*1024]
static __device__ __half g_vts[2][16777216];  // V^T split [128 z][512 l][256 t]
static __device__ __half g_as [2][8388608];   // attn split [128 z][256 s][256 t]

// smem: 3 stages x 4 planes; plane = 128 rows x 64B (XOR swizzled) = 8192B
#define PLANE 8192
#define STAGE 32768
#define SMEM_BYTES 98304

#define MMA_F16(d, a0, a1, a2, a3, b0, b1)                                     \
    asm volatile(                                                              \
        "mma.sync.aligned.m16n8k16.row.col.f32.f16.f16.f32 "                   \
        "{%0,%1,%2,%3},{%4,%5,%6,%7},{%8,%9},{%0,%1,%2,%3};"                   \
        : "+f"((d)[0]), "+f"((d)[1]), "+f"((d)[2]), "+f"((d)[3])               \
        : "r"(a0), "r"(a1), "r"(a2), "r"(a3), "r"(b0), "r"(b1))

#define LDSM4(r, addr)                                                         \
    asm volatile("ldmatrix.sync.aligned.m8n8.x4.shared.b16 {%0,%1,%2,%3}, [%4];" \
                 : "=r"((r)[0]), "=r"((r)[1]), "=r"((r)[2]), "=r"((r)[3])      \
                 : "r"(addr))

#define CP16(dst, src)                                                         \
    asm volatile("cp.async.cg.shared.global [%0], [%1], 16;"                   \
                 :: "r"(dst), "l"(src))
#define CP_COMMIT() asm volatile("cp.async.commit_group;" ::: "memory")
#define CP_WAIT(n)  asm volatile("cp.async.wait_group %0;" :: "n"(n) : "memory")

__device__ __forceinline__ uint32_t smem_u32(const void* p) {
    uint32_t a;
    asm("{ .reg .u64 t; cvta.to.shared.u64 t, %1; cvt.u32.u64 %0, t; }" : "=r"(a) : "l"(p));
    return a;
}

// swizzled byte offset of 16B-unit u in row r (64B rows)
__device__ __forceinline__ uint32_t swz(int r, int u) {
    return (uint32_t)(r * 64 + ((u ^ ((r >> 1) & 3)) << 4));
}

struct GP {
    const __half *Ah, *Al; int lda; long long Ao, Ai;
    const __half *Bh, *Bl; int ldb; long long Bo, Bi;
    float* C; int ldc; long long Co, Ci;        // mode 0 output
    __half *Ch, *Cl;                            // mode 1: Q|K split output
    __half *vth, *vtl;                          // mode 2: V^T split output
    const float* bias;
    float alpha;
    int K;
    int mode;     // 0 = f32 C; 1 = split C (QK); 2 = V^T split (vt col = bcol)
};

// ---------------------------------------------------------------------------
__global__ __launch_bounds__(256, 2) void gemm_tc(GP P)
{
    extern __shared__ char smem[];
    const uint32_t sb = smem_u32(smem);

    const int tid = threadIdx.x, lane = tid & 31, wid = tid >> 5;
    const int gid = lane >> 2, tig = lane & 3;
    const int wm = wid & 3, wn = wid >> 2;
    const int lrow = lane & 15;
    const int lu   = lane >> 4;

    const long long zq = blockIdx.z >> 3, zr = blockIdx.z & 7;
    const int brow = blockIdx.y * 128, bcol = blockIdx.x * 128;

    // ---- running cp.async source pointers (advance +32 halves per chunk) ----
    const int cr = tid >> 2, cu = tid & 3;
    const uint32_t csw = swz(cr, cu);                 // swz(cr+64,cu) = csw+4096
    const __half* pAh0 = P.Ah + zq * P.Ao + zr * P.Ai +
                         (long long)(brow + cr) * P.lda + cu * 8;
    const __half* pAl0 = P.Al + zq * P.Ao + zr * P.Ai +
                         (long long)(brow + cr) * P.lda + cu * 8;
    const __half* pBh0 = P.Bh + zq * P.Bo + zr * P.Bi +
                         (long long)(bcol + cr) * P.ldb + cu * 8;
    const __half* pBl0 = P.Bl + zq * P.Bo + zr * P.Bi +
                         (long long)(bcol + cr) * P.ldb + cu * 8;
    const __half* pAh1 = pAh0 + (long long)64 * P.lda;
    const __half* pAl1 = pAl0 + (long long)64 * P.lda;
    const __half* pBh1 = pBh0 + (long long)64 * P.ldb;
    const __half* pBl1 = pBl0 + (long long)64 * P.ldb;

    float acc[2][8][4];
#pragma unroll
    for (int i = 0; i < 2; i++)
#pragma unroll
        for (int j = 0; j < 8; j++)
#pragma unroll
            for (int q = 0; q < 4; q++) acc[i][j][q] = 0.0f;

    const int NC = P.K >> 5;

    auto load_chunk = [&](uint32_t stByte) {
        const uint32_t base = sb + stByte;
        uint32_t d0 = base + csw, d1 = base + csw + 4096;
        CP16(d0,             pAh0);
        CP16(d0 + PLANE,     pAl0);
        CP16(d0 + 2 * PLANE, pBh0);
        CP16(d0 + 3 * PLANE, pBl0);
        CP16(d1,             pAh1);
        CP16(d1 + PLANE,     pAl1);
        CP16(d1 + 2 * PLANE, pBh1);
        CP16(d1 + 3 * PLANE, pBl1);
        CP_COMMIT();
        pAh0 += 32; pAl0 += 32; pBh0 += 32; pBl0 += 32;
        pAh1 += 32; pAl1 += 32; pBh1 += 32; pBl1 += 32;
    };

    // ---- precomputed LDSM offsets (swizzle linear in 16-row steps) ----
    const int ar0 = wm * 32 + lrow;
    const int br0 = wn * 64 + lrow;
    const uint32_t aoff0 = swz(ar0, lu),     aoff1 = swz(ar0, 2 + lu);
    const uint32_t boff0 = swz(br0, lu) + 2 * PLANE;
    const uint32_t boff1 = swz(br0, 2 + lu) + 2 * PLANE;

    // one k16 step: LDSM fragments + 48 HMMAs (term-major)
    auto compute_ks = [&](uint32_t base, int ks) {
        const uint32_t ab = base + (ks ? aoff1 : aoff0);
        const uint32_t bb = base + (ks ? boff1 : boff0);
        uint32_t aH[2][4], aL[2][4];
#pragma unroll
        for (int mi = 0; mi < 2; mi++) {
            uint32_t ad = ab + mi * 1024;
            LDSM4(aH[mi], ad);
            LDSM4(aL[mi], ad + PLANE);
        }
#pragma unroll
        for (int jj = 0; jj < 4; jj++) {
            uint32_t bd = bb + jj * 1024;
            uint32_t bh[4], bl[4];
            LDSM4(bh, bd);
            LDSM4(bl, bd + PLANE);
#pragma unroll
            for (int e = 0; e < 2; e++)
#pragma unroll
                for (int mi = 0; mi < 2; mi++)
                    MMA_F16(acc[mi][jj * 2 + e],
                            aH[mi][0], aH[mi][1], aH[mi][2], aH[mi][3],
                            bh[e], bh[2 + e]);
#pragma unroll
            for (int e = 0; e < 2; e++)
#pragma unroll
                for (int mi = 0; mi < 2; mi++)
                    MMA_F16(acc[mi][jj * 2 + e],
                            aH[mi][0], aH[mi][1], aH[mi][2], aH[mi][3],
                            bl[e], bl[2 + e]);
#pragma unroll
            for (int e = 0; e < 2; e++)
#pragma unroll
                for (int mi = 0; mi < 2; mi++)
                    MMA_F16(acc[mi][jj * 2 + e],
                            aL[mi][0], aL[mi][1], aL[mi][2], aL[mi][3],
                            bh[e], bh[2 + e]);
        }
    };

    // one pipeline step: barrier -> compute ks0 -> issue next load -> ks1
    auto step = [&](int c, uint32_t stByte, uint32_t ldByte) {
        CP_WAIT(1);
        __syncthreads();
        const uint32_t base = sb + stByte;
        compute_ks(base, 0);
        if (c + 2 < NC) load_chunk(ldByte);
        else            CP_COMMIT();
        compute_ks(base, 1);
    };

    // 3-stage ring, unrolled so stage offsets are compile-time constants
    load_chunk(0);
    load_chunk(STAGE);
    int c = 0;
#pragma unroll 1
    for (; c + 3 <= NC; c += 3) {
        step(c,     0,         2 * STAGE);
        step(c + 1, STAGE,     0);
        step(c + 2, 2 * STAGE, STAGE);
    }
    if (c < NC) { step(c, 0, 2 * STAGE); c++; }
    if (c < NC) { step(c, STAGE, 0); }

    // ---------------- epilogue ----------------
    if (P.mode == 0) {
        float* C = P.C + zq * P.Co + zr * P.Ci;
#pragma unroll
        for (int mi = 0; mi < 2; mi++) {
#pragma unroll
            for (int j = 0; j < 8; j++) {
                int rl  = wm * 32 + mi * 16 + gid;
                int col = wn * 64 + j * 8 + tig * 2;
                float2 v0 = make_float2(acc[mi][j][0] * P.alpha, acc[mi][j][1] * P.alpha);
                float2 v1 = make_float2(acc[mi][j][2] * P.alpha, acc[mi][j][3] * P.alpha);
                *(float2*)(C + (long long)(brow + rl) * P.ldc + bcol + col)     = v0;
                *(float2*)(C + (long long)(brow + rl + 8) * P.ldc + bcol + col) = v1;
            }
        }
    } else if (P.mode == 1) {
        // Q|K tile -> split halves into Ch/Cl (ldc = 1024)
#pragma unroll
        for (int mi = 0; mi < 2; mi++) {
#pragma unroll
            for (int j = 0; j < 8; j++) {
                int rl  = wm * 32 + mi * 16 + gid;
                int col = wn * 64 + j * 8 + tig * 2;
                float bx = P.bias[bcol + col], by = P.bias[bcol + col + 1];
#pragma unroll
                for (int h = 0; h < 2; h++) {
                    float v0 = acc[mi][j][2 * h + 0] + bx;
                    float v1 = acc[mi][j][2 * h + 1] + by;
                    __half h0 = __float2half_rn(v0), h1 = __float2half_rn(v1);
                    long long o = (long long)(brow + rl + 8 * h) * 1024 + bcol + col;
                    *(__half2*)(P.Ch + o) = __halves2half2(h0, h1);
                    *(__half2*)(P.Cl + o) = __halves2half2(
                        __float2half_rn(v0 - __half2float(h0)),
                        __float2half_rn(v1 - __half2float(h1)));
                }
            }
        }
    } else {
        // V tile: bias-add, transpose via f32 smem staging, split into vth/vtl
        float* stg = (float*)smem;          // [128][129] = 66048B
        __syncthreads();
#pragma unroll
        for (int mi = 0; mi < 2; mi++) {
#pragma unroll
            for (int j = 0; j < 8; j++) {
                int rl  = wm * 32 + mi * 16 + gid;
                int col = wn * 64 + j * 8 + tig * 2;
                float bx = P.bias[bcol + col], by = P.bias[bcol + col + 1];
                stg[rl * 129 + col]           = acc[mi][j][0] + bx;
                stg[rl * 129 + col + 1]       = acc[mi][j][1] + by;
                stg[(rl + 8) * 129 + col]     = acc[mi][j][2] + bx;
                stg[(rl + 8) * 129 + col + 1] = acc[mi][j][3] + by;
            }
        }
        __syncthreads();
        const int z2 = brow >> 8;
        const int t0 = brow & 255;
        long long base = (long long)z2 * 131072 + (long long)bcol * 256 + t0;
        for (int idx = tid; idx < 16384; idx += 256) {
            int l = idx >> 7, m = idx & 127;
            float v = stg[m * 129 + l];
            __half h = __float2half_rn(v);
            long long o = base + (long long)l * 256 + m;
            P.vth[o] = h;
            P.vtl[o] = __float2half_rn(v - __half2float(h));
        }
    }
}

// ---------------------------------------------------------------------------
__global__ void split_kernel(const float* __restrict__ src,
                             __half* __restrict__ hi, __half* __restrict__ lo,
                             int n4)
{
    int i = blockIdx.x * blockDim.x + threadIdx.x;
    if (i >= n4) return;
    float4 v = ((const float4*)src)[i];
    __half h0 = __float2half_rn(v.x), h1 = __float2half_rn(v.y);
    __half h2 = __float2half_rn(v.z), h3 = __float2half_rn(v.w);
    ((__half2*)hi)[2 * i]     = __halves2half2(h0, h1);
    ((__half2*)hi)[2 * i + 1] = __halves2half2(h2, h3);
    ((__half2*)lo)[2 * i]     = __halves2half2(
        __float2half_rn(v.x - __half2float(h0)),
        __float2half_rn(v.y - __half2float(h1)));
    ((__half2*)lo)[2 * i + 1] = __halves2half2(
        __float2half_rn(v.z - __half2float(h2)),
        __float2half_rn(v.w - __half2float(h3)));
}

// ---------------------------------------------------------------------------
// Zero out_mat EXCEPT the diagonal blocks (those are fully written by the
// scores GEMM + softmax; writes are address-disjoint so this can run
// concurrently with the whole pipeline).
__global__ void fill_offdiag_kernel(float4* __restrict__ p)
{
    long long i = (long long)blockIdx.x * blockDim.x + threadIdx.x;
    const long long stride = (long long)gridDim.x * blockDim.x;
    const float4 z = make_float4(0.f, 0.f, 0.f, 0.f);
    for (; i < 16777216LL; i += stride) {
        int col4 = (int)(i & 511);
        int d    = (int)((i >> 17) & 7);            // (row >> 8) & 7, row = i >> 9
        if ((col4 >> 6) != d) p[i] = z;
    }
}

// ---------------------------------------------------------------------------
__global__ __launch_bounds__(256) void softmax_mask_kernel(
    float* __restrict__ out_mat, const int* __restrict__ n_ptr,
    __half* __restrict__ ah, __half* __restrict__ al)
{
    const int gwarp = ((blockIdx.x * blockDim.x) + threadIdx.x) >> 5;
    const int lane  = threadIdx.x & 31;
    const int s  = gwarp & 255;
    const int bd = gwarp >> 8;
    const int d  = bd & 7;
    const int b  = bd >> 3;

    float* row = out_mat + ((long long)(b * 2048 + d * 256 + s)) * 2048 + d * 256;
    long long abase = (long long)bd * 65536 + (long long)s * 256;

    float vals[8];
    float maxv = -INFINITY;
#pragma unroll
    for (int i = 0; i < 8; i++) {
        vals[i] = row[lane + i * 32];
        maxv = fmaxf(maxv, vals[i]);
    }
#pragma unroll
    for (int off = 16; off; off >>= 1)
        maxv = fmaxf(maxv, __shfl_xor_sync(0xFFFFFFFFu, maxv, off));

    float sum = 0.0f;
#pragma unroll
    for (int i = 0; i < 8; i++) { vals[i] = __expf(vals[i] - maxv); sum += vals[i]; }
#pragma unroll
    for (int off = 16; off; off >>= 1)
        sum += __shfl_xor_sync(0xFFFFFFFFu, sum, off);

    const float inv = 1.0f / sum;
    const int n = *n_ptr;
#pragma unroll
    for (int i = 0; i < 8; i++) {
        int t  = lane + i * 32;
        int ds = abs(t - s);
        bool masked = (ds == 0) || (ds >= 1 && (long long)ds * n <= 256);
        float v = masked ? 0.0f : vals[i] * inv;
        row[t] = v;
        __half h = __float2half_rn(v);
        ah[abase + t] = h;
        al[abase + t] = __float2half_rn(v - __half2float(h));
    }
}

// ---------------------------------------------------------------------------
extern "C" void kernel_launch(void* const* d_in, const int* in_sizes, int n_in,
                              void* d_out, int out_size)
{
    const float* x  = (const float*)d_in[0];
    const float* W  = (const float*)d_in[1];
    const float* bq = (const float*)d_in[2];
    const int* n_p  = (const int*)d_in[3];

    float* out     = (float*)d_out;
    float* out_mat = out + 16777216LL;

    __half *xs0, *xs1, *ws0, *ws1, *qk0, *qk1, *vt0, *vt1, *as0, *as1;
    cudaGetSymbolAddress((void**)&xs0, g_xs);  xs1 = xs0 + 16777216;
    cudaGetSymbolAddress((void**)&ws0, g_ws);  ws1 = ws0 + 786432;
    cudaGetSymbolAddress((void**)&qk0, g_qks); qk1 = qk0 + 33554432;
    cudaGetSymbolAddress((void**)&vt0, g_vts); vt1 = vt0 + 16777216;
    cudaGetSymbolAddress((void**)&as0, g_as);  as1 = as0 + 8388608;

    cudaFuncSetAttribute(gemm_tc, cudaFuncAttributeMaxDynamicSharedMemorySize, SMEM_BYTES);

    // one-time streams + events (created on the uncaptured correctness call)
    static cudaStream_t s1 = nullptr, s2 = nullptr;
    static cudaEvent_t evFork = nullptr, evJoin = nullptr,
                       evSplit = nullptr, evV = nullptr;
    if (!s1) {
        int prLo = 0, prHi = 0;
        cudaDeviceGetStreamPriorityRange(&prLo, &prHi);   // prLo = least urgent
        cudaStreamCreateWithPriority(&s1, cudaStreamNonBlocking, prLo);
        cudaStreamCreateWithFlags(&s2, cudaStreamNonBlocking);
        cudaEventCreateWithFlags(&evFork, cudaEventDisableTiming);
        cudaEventCreateWithFlags(&evJoin, cudaEventDisableTiming);
        cudaEventCreateWithFlags(&evSplit, cudaEventDisableTiming);
        cudaEventCreateWithFlags(&evV, cudaEventDisableTiming);
    }

    // ---- fork 1: off-diagonal zero-fill on low-priority s1 (joined at end)
    cudaEventRecord(evFork, 0);
    cudaStreamWaitEvent(s1, evFork, 0);
    fill_offdiag_kernel<<<8192, 256, 0, s1>>>((float4*)out_mat);
    cudaEventRecord(evJoin, s1);

    // 0) split x and W into half planes (main stream)
    split_kernel<<<16384, 256>>>(x, xs0, xs1, 4194304);
    split_kernel<<<768, 256>>>(W, ws0, ws1, 196608);
    cudaEventRecord(evSplit, 0);

    // ---- fork 2: V-proj on s2 — independent of QK-proj/scores/softmax,
    // fills their idle tail waves. V rows of W are 1024..1535 (K-major).
    cudaStreamWaitEvent(s2, evSplit, 0);
    {
        GP P = {};
        P.Ah = xs0; P.Al = xs1; P.lda = 512;  P.Ao = 0; P.Ai = 0;
        P.Bh = ws0 + 1024 * 512; P.Bl = ws1 + 1024 * 512;
        P.ldb = 512; P.Bo = 0; P.Bi = 0;
        P.vth = vt0; P.vtl = vt1;
        P.bias = bq + 1024; P.alpha = 1.0f; P.K = 512; P.mode = 2;
        gemm_tc<<<dim3(4, 256, 1), 256, SMEM_BYTES, s2>>>(P);
    }
    cudaEventRecord(evV, s2);

    // 2) QK-proj: Q|K -> g_qks split (main stream)
    {
        GP P = {};
        P.Ah = xs0; P.Al = xs1; P.lda = 512;  P.Ao = 0; P.Ai = 0;
        P.Bh = ws0; P.Bl = ws1; P.ldb = 512;  P.Bo = 0; P.Bi = 0;
        P.Ch = qk0; P.Cl = qk1;
        P.bias = bq; P.alpha = 1.0f; P.K = 512; P.mode = 1;
        gemm_tc<<<dim3(8, 256, 1), 256, SMEM_BYTES>>>(P);
    }

    // 3) scores = Q K^T / sqrt(512) -> diagonal blocks of out_mat (f32)
    {
        GP P = {};
        P.Ah = qk0;       P.Al = qk1;       P.lda = 1024; P.Ao = 8LL * 262144; P.Ai = 262144;
        P.Bh = qk0 + 512; P.Bl = qk1 + 512; P.ldb = 1024; P.Bo = 8LL * 262144; P.Bi = 262144;
        P.C = out_mat; P.ldc = 2048; P.Co = 4194304; P.Ci = 524544;
        P.alpha = 0.044194173824159216f; P.K = 512; P.mode = 0;
        gemm_tc<<<dim3(2, 2, 128), 256, SMEM_BYTES>>>(P);
    }

    // 4) softmax + mask; writes f32 attn + split-half attn
    softmax_mask_kernel<<<4096, 256>>>(out_mat, n_p, as0, as1);

    // ---- join V-proj before AV consumes g_vts
    cudaStreamWaitEvent(0, evV, 0);

    // 5) out = attn * V   (A = split attn, B = split V^T, both K-major over t)
    {
        GP P = {};
        P.Ah = as0; P.Al = as1; P.lda = 256; P.Ao = 8LL * 65536;  P.Ai = 65536;
        P.Bh = vt0; P.Bl = vt1; P.ldb = 256; P.Bo = 8LL * 131072; P.Bi = 131072;
        P.C = out; P.ldc = 512; P.Co = 1048576; P.Ci = 131072;
        P.alpha = 1.0f; P.K = 256; P.mode = 0;
        gemm_tc<<<dim3(4, 2, 128), 256, SMEM_BYTES>>>(P);
    }

    // ---- join: fill must complete before the launch's work is "done" ----
    cudaStreamWaitEvent(0, evJoin, 0);
}

// round 15
// speedup vs baseline: 1.0000x; 1.0000x over previous
#include <cuda_runtime.h>
#include <cuda_fp16.h>
#include <stdint.h>
#include <math.h>

// ---------------------------------------------------------------------------
// B=16, D=8, S=256, L=512.
//   x [32768,512] f32 | Wqkv [1536,512] | bqkv [1536] | n (int)
// d_out: output [16,2048,512] (16,777,216 f32) then out_mat [16,2048,2048].
//
// All GEMMs: legacy mma.sync.m16n8k16 fp16, 2-way split precision (hi+lo,
// 3 HMMAs per logical MMA). Operands pre-split to half planes.
// 3-stage cp.async ring (constant stage offsets), loads issued mid-compute,
// XOR-swizzled 64B-row smem tiles, ldmatrix fragments. (R9 compute config.)
// R15: V-proj forked AFTER QK-proj so it overlaps scores+softmax (not QK).
// Off-diagonal zero-fill stays on a low-priority stream, joined at the end.
// ---------------------------------------------------------------------------

static __device__ __half g_xs [2][16777216];  // x split planes [32768*512]
static __device__ __half g_ws [2][786432];    // Wqkv split planes [1536*512]
static __device__ __half g_qks[2][33554432];  // Q|K split [32768*1024]
static __device__ __half g_vts[2][16777216];  // V^T split [128 z][512 l][256 t]
static __device__ __half g_as [2][8388608];   // attn split [128 z][256 s][256 t]

// smem: 3 stages x 4 planes; plane = 128 rows x 64B (XOR swizzled) = 8192B
#define PLANE 8192
#define STAGE 32768
#define SMEM_BYTES 98304

#define MMA_F16(d, a0, a1, a2, a3, b0, b1)                                     \
    asm volatile(                                                              \
        "mma.sync.aligned.m16n8k16.row.col.f32.f16.f16.f32 "                   \
        "{%0,%1,%2,%3},{%4,%5,%6,%7},{%8,%9},{%0,%1,%2,%3};"                   \
        : "+f"((d)[0]), "+f"((d)[1]), "+f"((d)[2]), "+f"((d)[3])               \
        : "r"(a0), "r"(a1), "r"(a2), "r"(a3), "r"(b0), "r"(b1))

#define LDSM4(r, addr)                                                         \
    asm volatile("ldmatrix.sync.aligned.m8n8.x4.shared.b16 {%0,%1,%2,%3}, [%4];" \
                 : "=r"((r)[0]), "=r"((r)[1]), "=r"((r)[2]), "=r"((r)[3])      \
                 : "r"(addr))

#define CP16(dst, src)                                                         \
    asm volatile("cp.async.cg.shared.global [%0], [%1], 16;"                   \
                 :: "r"(dst), "l"(src))
#define CP_COMMIT() asm volatile("cp.async.commit_group;" ::: "memory")
#define CP_WAIT(n)  asm volatile("cp.async.wait_group %0;" :: "n"(n) : "memory")

__device__ __forceinline__ uint32_t smem_u32(const void* p) {
    uint32_t a;
    asm("{ .reg .u64 t; cvta.to.shared.u64 t, %1; cvt.u32.u64 %0, t; }" : "=r"(a) : "l"(p));
    return a;
}

// swizzled byte offset of 16B-unit u in row r (64B rows)
__device__ __forceinline__ uint32_t swz(int r, int u) {
    return (uint32_t)(r * 64 + ((u ^ ((r >> 1) & 3)) << 4));
}

struct GP {
    const __half *Ah, *Al; int lda; long long Ao, Ai;
    const __half *Bh, *Bl; int ldb; long long Bo, Bi;
    float* C; int ldc; long long Co, Ci;        // mode 0 output
    __half *Ch, *Cl;                            // mode 1: Q|K split output
    __half *vth, *vtl;                          // mode 2: V^T split output
    const float* bias;
    float alpha;
    int K;
    int mode;     // 0 = f32 C; 1 = split C (QK); 2 = V^T split (vt col = bcol)
};

// ---------------------------------------------------------------------------
__global__ __launch_bounds__(256, 2) void gemm_tc(GP P)
{
    extern __shared__ char smem[];
    const uint32_t sb = smem_u32(smem);

    const int tid = threadIdx.x, lane = tid & 31, wid = tid >> 5;
    const int gid = lane >> 2, tig = lane & 3;
    const int wm = wid & 3, wn = wid >> 2;
    const int lrow = lane & 15;
    const int lu   = lane >> 4;

    const long long zq = blockIdx.z >> 3, zr = blockIdx.z & 7;
    const int brow = blockIdx.y * 128, bcol = blockIdx.x * 128;

    // ---- running cp.async source pointers (advance +32 halves per chunk) ----
    const int cr = tid >> 2, cu = tid & 3;
    const uint32_t csw = swz(cr, cu);                 // swz(cr+64,cu) = csw+4096
    const __half* pAh0 = P.Ah + zq * P.Ao + zr * P.Ai +
                         (long long)(brow + cr) * P.lda + cu * 8;
    const __half* pAl0 = P.Al + zq * P.Ao + zr * P.Ai +
                         (long long)(brow + cr) * P.lda + cu * 8;
    const __half* pBh0 = P.Bh + zq * P.Bo + zr * P.Bi +
                         (long long)(bcol + cr) * P.ldb + cu * 8;
    const __half* pBl0 = P.Bl + zq * P.Bo + zr * P.Bi +
                         (long long)(bcol + cr) * P.ldb + cu * 8;
    const __half* pAh1 = pAh0 + (long long)64 * P.lda;
    const __half* pAl1 = pAl0 + (long long)64 * P.lda;
    const __half* pBh1 = pBh0 + (long long)64 * P.ldb;
    const __half* pBl1 = pBl0 + (long long)64 * P.ldb;

    float acc[2][8][4];
#pragma unroll
    for (int i = 0; i < 2; i++)
#pragma unroll
        for (int j = 0; j < 8; j++)
#pragma unroll
            for (int q = 0; q < 4; q++) acc[i][j][q] = 0.0f;

    const int NC = P.K >> 5;

    auto load_chunk = [&](uint32_t stByte) {
        const uint32_t base = sb + stByte;
        uint32_t d0 = base + csw, d1 = base + csw + 4096;
        CP16(d0,             pAh0);
        CP16(d0 + PLANE,     pAl0);
        CP16(d0 + 2 * PLANE, pBh0);
        CP16(d0 + 3 * PLANE, pBl0);
        CP16(d1,             pAh1);
        CP16(d1 + PLANE,     pAl1);
        CP16(d1 + 2 * PLANE, pBh1);
        CP16(d1 + 3 * PLANE, pBl1);
        CP_COMMIT();
        pAh0 += 32; pAl0 += 32; pBh0 += 32; pBl0 += 32;
        pAh1 += 32; pAl1 += 32; pBh1 += 32; pBl1 += 32;
    };

    // ---- precomputed LDSM offsets (swizzle linear in 16-row steps) ----
    const int ar0 = wm * 32 + lrow;
    const int br0 = wn * 64 + lrow;
    const uint32_t aoff0 = swz(ar0, lu),     aoff1 = swz(ar0, 2 + lu);
    const uint32_t boff0 = swz(br0, lu) + 2 * PLANE;
    const uint32_t boff1 = swz(br0, 2 + lu) + 2 * PLANE;

    // one k16 step: LDSM fragments + 48 HMMAs (term-major)
    auto compute_ks = [&](uint32_t base, int ks) {
        const uint32_t ab = base + (ks ? aoff1 : aoff0);
        const uint32_t bb = base + (ks ? boff1 : boff0);
        uint32_t aH[2][4], aL[2][4];
#pragma unroll
        for (int mi = 0; mi < 2; mi++) {
            uint32_t ad = ab + mi * 1024;
            LDSM4(aH[mi], ad);
            LDSM4(aL[mi], ad + PLANE);
        }
#pragma unroll
        for (int jj = 0; jj < 4; jj++) {
            uint32_t bd = bb + jj * 1024;
            uint32_t bh[4], bl[4];
            LDSM4(bh, bd);
            LDSM4(bl, bd + PLANE);
#pragma unroll
            for (int e = 0; e < 2; e++)
#pragma unroll
                for (int mi = 0; mi < 2; mi++)
                    MMA_F16(acc[mi][jj * 2 + e],
                            aH[mi][0], aH[mi][1], aH[mi][2], aH[mi][3],
                            bh[e], bh[2 + e]);
#pragma unroll
            for (int e = 0; e < 2; e++)
#pragma unroll
                for (int mi = 0; mi < 2; mi++)
                    MMA_F16(acc[mi][jj * 2 + e],
                            aH[mi][0], aH[mi][1], aH[mi][2], aH[mi][3],
                            bl[e], bl[2 + e]);
#pragma unroll
            for (int e = 0; e < 2; e++)
#pragma unroll
                for (int mi = 0; mi < 2; mi++)
                    MMA_F16(acc[mi][jj * 2 + e],
                            aL[mi][0], aL[mi][1], aL[mi][2], aL[mi][3],
                            bh[e], bh[2 + e]);
        }
    };

    // one pipeline step: barrier -> compute ks0 -> issue next load -> ks1
    auto step = [&](int c, uint32_t stByte, uint32_t ldByte) {
        CP_WAIT(1);
        __syncthreads();
        const uint32_t base = sb + stByte;
        compute_ks(base, 0);
        if (c + 2 < NC) load_chunk(ldByte);
        else            CP_COMMIT();
        compute_ks(base, 1);
    };

    // 3-stage ring, unrolled so stage offsets are compile-time constants
    load_chunk(0);
    load_chunk(STAGE);
    int c = 0;
#pragma unroll 1
    for (; c + 3 <= NC; c += 3) {
        step(c,     0,         2 * STAGE);
        step(c + 1, STAGE,     0);
        step(c + 2, 2 * STAGE, STAGE);
    }
    if (c < NC) { step(c, 0, 2 * STAGE); c++; }
    if (c < NC) { step(c, STAGE, 0); }

    // ---------------- epilogue ----------------
    if (P.mode == 0) {
        float* C = P.C + zq * P.Co + zr * P.Ci;
#pragma unroll
        for (int mi = 0; mi < 2; mi++) {
#pragma unroll
            for (int j = 0; j < 8; j++) {
                int rl  = wm * 32 + mi * 16 + gid;
                int col = wn * 64 + j * 8 + tig * 2;
                float2 v0 = make_float2(acc[mi][j][0] * P.alpha, acc[mi][j][1] * P.alpha);
                float2 v1 = make_float2(acc[mi][j][2] * P.alpha, acc[mi][j][3] * P.alpha);
                *(float2*)(C + (long long)(brow + rl) * P.ldc + bcol + col)     = v0;
                *(float2*)(C + (long long)(brow + rl + 8) * P.ldc + bcol + col) = v1;
            }
        }
    } else if (P.mode == 1) {
        // Q|K tile -> split halves into Ch/Cl (ldc = 1024)
#pragma unroll
        for (int mi = 0; mi < 2; mi++) {
#pragma unroll
            for (int j = 0; j < 8; j++) {
                int rl  = wm * 32 + mi * 16 + gid;
                int col = wn * 64 + j * 8 + tig * 2;
                float bx = P.bias[bcol + col], by = P.bias[bcol + col + 1];
#pragma unroll
                for (int h = 0; h < 2; h++) {
                    float v0 = acc[mi][j][2 * h + 0] + bx;
                    float v1 = acc[mi][j][2 * h + 1] + by;
                    __half h0 = __float2half_rn(v0), h1 = __float2half_rn(v1);
                    long long o = (long long)(brow + rl + 8 * h) * 1024 + bcol + col;
                    *(__half2*)(P.Ch + o) = __halves2half2(h0, h1);
                    *(__half2*)(P.Cl + o) = __halves2half2(
                        __float2half_rn(v0 - __half2float(h0)),
                        __float2half_rn(v1 - __half2float(h1)));
                }
            }
        }
    } else {
        // V tile: bias-add, transpose via f32 smem staging, split into vth/vtl
        float* stg = (float*)smem;          // [128][129] = 66048B
        __syncthreads();
#pragma unroll
        for (int mi = 0; mi < 2; mi++) {
#pragma unroll
            for (int j = 0; j < 8; j++) {
                int rl  = wm * 32 + mi * 16 + gid;
                int col = wn * 64 + j * 8 + tig * 2;
                float bx = P.bias[bcol + col], by = P.bias[bcol + col + 1];
                stg[rl * 129 + col]           = acc[mi][j][0] + bx;
                stg[rl * 129 + col + 1]       = acc[mi][j][1] + by;
                stg[(rl + 8) * 129 + col]     = acc[mi][j][2] + bx;
                stg[(rl + 8) * 129 + col + 1] = acc[mi][j][3] + by;
            }
        }
        __syncthreads();
        const int z2 = brow >> 8;
        const int t0 = brow & 255;
        long long base = (long long)z2 * 131072 + (long long)bcol * 256 + t0;
        for (int idx = tid; idx < 16384; idx += 256) {
            int l = idx >> 7, m = idx & 127;
            float v = stg[m * 129 + l];
            __half h = __float2half_rn(v);
            long long o = base + (long long)l * 256 + m;
            P.vth[o] = h;
            P.vtl[o] = __float2half_rn(v - __half2float(h));
        }
    }
}

// ---------------------------------------------------------------------------
__global__ void split_kernel(const float* __restrict__ src,
                             __half* __restrict__ hi, __half* __restrict__ lo,
                             int n4)
{
    int i = blockIdx.x * blockDim.x + threadIdx.x;
    if (i >= n4) return;
    float4 v = ((const float4*)src)[i];
    __half h0 = __float2half_rn(v.x), h1 = __float2half_rn(v.y);
    __half h2 = __float2half_rn(v.z), h3 = __float2half_rn(v.w);
    ((__half2*)hi)[2 * i]     = __halves2half2(h0, h1);
    ((__half2*)hi)[2 * i + 1] = __halves2half2(h2, h3);
    ((__half2*)lo)[2 * i]     = __halves2half2(
        __float2half_rn(v.x - __half2float(h0)),
        __float2half_rn(v.y - __half2float(h1)));
    ((__half2*)lo)[2 * i + 1] = __halves2half2(
        __float2half_rn(v.z - __half2float(h2)),
        __float2half_rn(v.w - __half2float(h3)));
}

// ---------------------------------------------------------------------------
// Zero out_mat EXCEPT the diagonal blocks (those are fully written by the
// scores GEMM + softmax; writes are address-disjoint so this can run
// concurrently with the whole pipeline).
__global__ void fill_offdiag_kernel(float4* __restrict__ p)
{
    long long i = (long long)blockIdx.x * blockDim.x + threadIdx.x;
    const long long stride = (long long)gridDim.x * blockDim.x;
    const float4 z = make_float4(0.f, 0.f, 0.f, 0.f);
    for (; i < 16777216LL; i += stride) {
        int col4 = (int)(i & 511);
        int d    = (int)((i >> 17) & 7);            // (row >> 8) & 7, row = i >> 9
        if ((col4 >> 6) != d) p[i] = z;
    }
}

// ---------------------------------------------------------------------------
__global__ __launch_bounds__(256) void softmax_mask_kernel(
    float* __restrict__ out_mat, const int* __restrict__ n_ptr,
    __half* __restrict__ ah, __half* __restrict__ al)
{
    const int gwarp = ((blockIdx.x * blockDim.x) + threadIdx.x) >> 5;
    const int lane  = threadIdx.x & 31;
    const int s  = gwarp & 255;
    const int bd = gwarp >> 8;
    const int d  = bd & 7;
    const int b  = bd >> 3;

    float* row = out_mat + ((long long)(b * 2048 + d * 256 + s)) * 2048 + d * 256;
    long long abase = (long long)bd * 65536 + (long long)s * 256;

    float vals[8];
    float maxv = -INFINITY;
#pragma unroll
    for (int i = 0; i < 8; i++) {
        vals[i] = row[lane + i * 32];
        maxv = fmaxf(maxv, vals[i]);
    }
#pragma unroll
    for (int off = 16; off; off >>= 1)
        maxv = fmaxf(maxv, __shfl_xor_sync(0xFFFFFFFFu, maxv, off));

    float sum = 0.0f;
#pragma unroll
    for (int i = 0; i < 8; i++) { vals[i] = __expf(vals[i] - maxv); sum += vals[i]; }
#pragma unroll
    for (int off = 16; off; off >>= 1)
        sum += __shfl_xor_sync(0xFFFFFFFFu, sum, off);

    const float inv = 1.0f / sum;
    const int n = *n_ptr;
#pragma unroll
    for (int i = 0; i < 8; i++) {
        int t  = lane + i * 32;
        int ds = abs(t - s);
        bool masked = (ds == 0) || (ds >= 1 && (long long)ds * n <= 256);
        float v = masked ? 0.0f : vals[i] * inv;
        row[t] = v;
        __half h = __float2half_rn(v);
        ah[abase + t] = h;
        al[abase + t] = __float2half_rn(v - __half2float(h));
    }
}

// ---------------------------------------------------------------------------
extern "C" void kernel_launch(void* const* d_in, const int* in_sizes, int n_in,
                              void* d_out, int out_size)
{
    const float* x  = (const float*)d_in[0];
    const float* W  = (const float*)d_in[1];
    const float* bq = (const float*)d_in[2];
    const int* n_p  = (const int*)d_in[3];

    float* out     = (float*)d_out;
    float* out_mat = out + 16777216LL;

    __half *xs0, *xs1, *ws0, *ws1, *qk0, *qk1, *vt0, *vt1, *as0, *as1;
    cudaGetSymbolAddress((void**)&xs0, g_xs);  xs1 = xs0 + 16777216;
    cudaGetSymbolAddress((void**)&ws0, g_ws);  ws1 = ws0 + 786432;
    cudaGetSymbolAddress((void**)&qk0, g_qks); qk1 = qk0 + 33554432;
    cudaGetSymbolAddress((void**)&vt0, g_vts); vt1 = vt0 + 16777216;
    cudaGetSymbolAddress((void**)&as0, g_as);  as1 = as0 + 8388608;

    cudaFuncSetAttribute(gemm_tc, cudaFuncAttributeMaxDynamicSharedMemorySize, SMEM_BYTES);

    // one-time streams + events (created on the uncaptured correctness call)
    static cudaStream_t s1 = nullptr, s2 = nullptr;
    static cudaEvent_t evFork = nullptr, evJoin = nullptr,
                       evQK = nullptr, evV = nullptr;
    if (!s1) {
        int prLo = 0, prHi = 0;
        cudaDeviceGetStreamPriorityRange(&prLo, &prHi);   // prLo = least urgent
        cudaStreamCreateWithPriority(&s1, cudaStreamNonBlocking, prLo);
        cudaStreamCreateWithFlags(&s2, cudaStreamNonBlocking);
        cudaEventCreateWithFlags(&evFork, cudaEventDisableTiming);
        cudaEventCreateWithFlags(&evJoin, cudaEventDisableTiming);
        cudaEventCreateWithFlags(&evQK, cudaEventDisableTiming);
        cudaEventCreateWithFlags(&evV, cudaEventDisableTiming);
    }

    // ---- fork 1: off-diagonal zero-fill on low-priority s1 (joined at end)
    cudaEventRecord(evFork, 0);
    cudaStreamWaitEvent(s1, evFork, 0);
    fill_offdiag_kernel<<<8192, 256, 0, s1>>>((float4*)out_mat);
    cudaEventRecord(evJoin, s1);

    // 0) split x and W into half planes (main stream)
    split_kernel<<<16384, 256>>>(x, xs0, xs1, 4194304);
    split_kernel<<<768, 256>>>(W, ws0, ws1, 196608);

    // 2) QK-proj: Q|K -> g_qks split (main stream)
    {
        GP P = {};
        P.Ah = xs0; P.Al = xs1; P.lda = 512;  P.Ao = 0; P.Ai = 0;
        P.Bh = ws0; P.Bl = ws1; P.ldb = 512;  P.Bo = 0; P.Bi = 0;
        P.Ch = qk0; P.Cl = qk1;
        P.bias = bq; P.alpha = 1.0f; P.K = 512; P.mode = 1;
        gemm_tc<<<dim3(8, 256, 1), 256, SMEM_BYTES>>>(P);
    }
    cudaEventRecord(evQK, 0);

    // ---- fork 2: V-proj on s2 AFTER QK-proj, so it overlaps the
    // scores+softmax phase (their tail waves / low occupancy), not QK-proj.
    cudaStreamWaitEvent(s2, evQK, 0);
    {
        GP P = {};
        P.Ah = xs0; P.Al = xs1; P.lda = 512;  P.Ao = 0; P.Ai = 0;
        P.Bh = ws0 + 1024 * 512; P.Bl = ws1 + 1024 * 512;
        P.ldb = 512; P.Bo = 0; P.Bi = 0;
        P.vth = vt0; P.vtl = vt1;
        P.bias = bq + 1024; P.alpha = 1.0f; P.K = 512; P.mode = 2;
        gemm_tc<<<dim3(4, 256, 1), 256, SMEM_BYTES, s2>>>(P);
    }
    cudaEventRecord(evV, s2);

    // 3) scores = Q K^T / sqrt(512) -> diagonal blocks of out_mat (f32)
    {
        GP P = {};
        P.Ah = qk0;       P.Al = qk1;       P.lda = 1024; P.Ao = 8LL * 262144; P.Ai = 262144;
        P.Bh = qk0 + 512; P.Bl = qk1 + 512; P.ldb = 1024; P.Bo = 8LL * 262144; P.Bi = 262144;
        P.C = out_mat; P.ldc = 2048; P.Co = 4194304; P.Ci = 524544;
        P.alpha = 0.044194173824159216f; P.K = 512; P.mode = 0;
        gemm_tc<<<dim3(2, 2, 128), 256, SMEM_BYTES>>>(P);
    }

    // 4) softmax + mask; writes f32 attn + split-half attn
    softmax_mask_kernel<<<4096, 256>>>(out_mat, n_p, as0, as1);

    // ---- join V-proj before AV consumes g_vts
    cudaStreamWaitEvent(0, evV, 0);

    // 5) out = attn * V   (A = split attn, B = split V^T, both K-major over t)
    {
        GP P = {};
        P.Ah = as0; P.Al = as1; P.lda = 256; P.Ao = 8LL * 65536;  P.Ai = 65536;
        P.Bh = vt0; P.Bl = vt1; P.ldb = 256; P.Bo = 8LL * 131072; P.Bi = 131072;
        P.C = out; P.ldc = 512; P.Co = 1048576; P.Ci = 131072;
        P.alpha = 1.0f; P.K = 256; P.mode = 0;
        gemm_tc<<<dim3(4, 2, 128), 256, SMEM_BYTES>>>(P);
    }

    // ---- join: fill must complete before the launch's work is "done" ----
    cudaStreamWaitEvent(0, evJoin, 0);
}

// round 16
// speedup vs baseline: 1.0646x; 1.0646x over previous
#include <cuda_runtime.h>
#include <cuda_fp16.h>
#include <stdint.h>
#include <math.h>

// ---------------------------------------------------------------------------
// B=16, D=8, S=256, L=512.
//   x [32768,512] f32 | Wqkv [1536,512] | bqkv [1536] | n (int)
// d_out: output [16,2048,512] (16,777,216 f32) then out_mat [16,2048,2048].
//
// All GEMMs: legacy mma.sync.m16n8k16 fp16 split precision. QKV/scores use
// 3 HMMAs per logical MMA (hh+hl+lh, fp32-grade); AV uses 2 (hh+hl) — attn
// is in [0,1] so the dropped lo_attn*V term contributes ~5e-4 global rel err,
// well under the 1e-3 gate. R13 pipeline structure (best known): monolithic
// QKV, off-diag fill on low-priority stream joined at end.
// ---------------------------------------------------------------------------

static __device__ __half g_xs [2][16777216];  // x split planes [32768*512]
static __device__ __half g_ws [2][786432];    // Wqkv split planes [1536*512]
static __device__ __half g_qks[2][33554432];  // Q|K split [32768*1024]
static __device__ __half g_vts[2][16777216];  // V^T split [128 z][512 l][256 t]
static __device__ __half g_as [2][8388608];   // attn split [128 z][256 s][256 t]

// smem: 3 stages x 4 planes; plane = 128 rows x 64B (XOR swizzled) = 8192B
#define PLANE 8192
#define STAGE 32768
#define SMEM_BYTES 98304

#define MMA_F16(d, a0, a1, a2, a3, b0, b1)                                     \
    asm volatile(                                                              \
        "mma.sync.aligned.m16n8k16.row.col.f32.f16.f16.f32 "                   \
        "{%0,%1,%2,%3},{%4,%5,%6,%7},{%8,%9},{%0,%1,%2,%3};"                   \
        : "+f"((d)[0]), "+f"((d)[1]), "+f"((d)[2]), "+f"((d)[3])               \
        : "r"(a0), "r"(a1), "r"(a2), "r"(a3), "r"(b0), "r"(b1))

#define LDSM4(r, addr)                                                         \
    asm volatile("ldmatrix.sync.aligned.m8n8.x4.shared.b16 {%0,%1,%2,%3}, [%4];" \
                 : "=r"((r)[0]), "=r"((r)[1]), "=r"((r)[2]), "=r"((r)[3])      \
                 : "r"(addr))

#define CP16(dst, src)                                                         \
    asm volatile("cp.async.cg.shared.global [%0], [%1], 16;"                   \
                 :: "r"(dst), "l"(src))
#define CP_COMMIT() asm volatile("cp.async.commit_group;" ::: "memory")
#define CP_WAIT(n)  asm volatile("cp.async.wait_group %0;" :: "n"(n) : "memory")

__device__ __forceinline__ uint32_t smem_u32(const void* p) {
    uint32_t a;
    asm("{ .reg .u64 t; cvta.to.shared.u64 t, %1; cvt.u32.u64 %0, t; }" : "=r"(a) : "l"(p));
    return a;
}

// swizzled byte offset of 16B-unit u in row r (64B rows)
__device__ __forceinline__ uint32_t swz(int r, int u) {
    return (uint32_t)(r * 64 + ((u ^ ((r >> 1) & 3)) << 4));
}

struct GP {
    const __half *Ah, *Al; int lda; long long Ao, Ai;
    const __half *Bh, *Bl; int ldb; long long Bo, Bi;
    float* C; int ldc; long long Co, Ci;        // mode 0 output
    __half *Ch, *Cl;                            // mode 1: Q|K split output
    __half *vth, *vtl;                          // mode 1: V^T split output
    const float* bias;
    float alpha;
    int K;
    int mode;     // 0 = f32 C; 1 = QKV (split C; bcol>=1024 -> vt transposed)
};

// ---------------------------------------------------------------------------
template <int TERMS>
__global__ __launch_bounds__(256, 2) void gemm_tc(GP P)
{
    extern __shared__ char smem[];
    const uint32_t sb = smem_u32(smem);

    const int tid = threadIdx.x, lane = tid & 31, wid = tid >> 5;
    const int gid = lane >> 2, tig = lane & 3;
    const int wm = wid & 3, wn = wid >> 2;
    const int lrow = lane & 15;
    const int lu   = lane >> 4;

    const long long zq = blockIdx.z >> 3, zr = blockIdx.z & 7;
    const int brow = blockIdx.y * 128, bcol = blockIdx.x * 128;

    // ---- running cp.async source pointers (advance +32 halves per chunk) ----
    const int cr = tid >> 2, cu = tid & 3;
    const uint32_t csw = swz(cr, cu);                 // swz(cr+64,cu) = csw+4096
    const __half* pAh0 = P.Ah + zq * P.Ao + zr * P.Ai +
                         (long long)(brow + cr) * P.lda + cu * 8;
    const __half* pAl0 = P.Al + zq * P.Ao + zr * P.Ai +
                         (long long)(brow + cr) * P.lda + cu * 8;
    const __half* pBh0 = P.Bh + zq * P.Bo + zr * P.Bi +
                         (long long)(bcol + cr) * P.ldb + cu * 8;
    const __half* pBl0 = P.Bl + zq * P.Bo + zr * P.Bi +
                         (long long)(bcol + cr) * P.ldb + cu * 8;
    const __half* pAh1 = pAh0 + (long long)64 * P.lda;
    const __half* pAl1 = pAl0 + (long long)64 * P.lda;
    const __half* pBh1 = pBh0 + (long long)64 * P.ldb;
    const __half* pBl1 = pBl0 + (long long)64 * P.ldb;

    float acc[2][8][4];
#pragma unroll
    for (int i = 0; i < 2; i++)
#pragma unroll
        for (int j = 0; j < 8; j++)
#pragma unroll
            for (int q = 0; q < 4; q++) acc[i][j][q] = 0.0f;

    const int NC = P.K >> 5;

    auto load_chunk = [&](uint32_t stByte) {
        const uint32_t base = sb + stByte;
        uint32_t d0 = base + csw, d1 = base + csw + 4096;
        CP16(d0,             pAh0);
        CP16(d0 + PLANE,     pAl0);
        CP16(d0 + 2 * PLANE, pBh0);
        CP16(d0 + 3 * PLANE, pBl0);
        CP16(d1,             pAh1);
        CP16(d1 + PLANE,     pAl1);
        CP16(d1 + 2 * PLANE, pBh1);
        CP16(d1 + 3 * PLANE, pBl1);
        CP_COMMIT();
        pAh0 += 32; pAl0 += 32; pBh0 += 32; pBl0 += 32;
        pAh1 += 32; pAl1 += 32; pBh1 += 32; pBl1 += 32;
    };

    // ---- precomputed LDSM offsets (swizzle linear in 16-row steps) ----
    const int ar0 = wm * 32 + lrow;
    const int br0 = wn * 64 + lrow;
    const uint32_t aoff0 = swz(ar0, lu),     aoff1 = swz(ar0, 2 + lu);
    const uint32_t boff0 = swz(br0, lu) + 2 * PLANE;
    const uint32_t boff1 = swz(br0, 2 + lu) + 2 * PLANE;

    // one k16 step: LDSM fragments + TERMS*32 HMMAs (term-major)
    auto compute_ks = [&](uint32_t base, int ks) {
        const uint32_t ab = base + (ks ? aoff1 : aoff0);
        const uint32_t bb = base + (ks ? boff1 : boff0);
        uint32_t aH[2][4], aL[2][4];
#pragma unroll
        for (int mi = 0; mi < 2; mi++) {
            uint32_t ad = ab + mi * 1024;
            LDSM4(aH[mi], ad);
            if (TERMS == 3) LDSM4(aL[mi], ad + PLANE);
        }
#pragma unroll
        for (int jj = 0; jj < 4; jj++) {
            uint32_t bd = bb + jj * 1024;
            uint32_t bh[4], bl[4];
            LDSM4(bh, bd);
            LDSM4(bl, bd + PLANE);
#pragma unroll
            for (int e = 0; e < 2; e++)
#pragma unroll
                for (int mi = 0; mi < 2; mi++)
                    MMA_F16(acc[mi][jj * 2 + e],
                            aH[mi][0], aH[mi][1], aH[mi][2], aH[mi][3],
                            bh[e], bh[2 + e]);
#pragma unroll
            for (int e = 0; e < 2; e++)
#pragma unroll
                for (int mi = 0; mi < 2; mi++)
                    MMA_F16(acc[mi][jj * 2 + e],
                            aH[mi][0], aH[mi][1], aH[mi][2], aH[mi][3],
                            bl[e], bl[2 + e]);
            if (TERMS == 3) {
#pragma unroll
                for (int e = 0; e < 2; e++)
#pragma unroll
                    for (int mi = 0; mi < 2; mi++)
                        MMA_F16(acc[mi][jj * 2 + e],
                                aL[mi][0], aL[mi][1], aL[mi][2], aL[mi][3],
                                bh[e], bh[2 + e]);
            }
        }
    };

    // one pipeline step: barrier -> compute ks0 -> issue next load -> ks1
    auto step = [&](int c, uint32_t stByte, uint32_t ldByte) {
        CP_WAIT(1);
        __syncthreads();
        const uint32_t base = sb + stByte;
        compute_ks(base, 0);
        if (c + 2 < NC) load_chunk(ldByte);
        else            CP_COMMIT();
        compute_ks(base, 1);
    };

    // 3-stage ring, unrolled so stage offsets are compile-time constants
    load_chunk(0);
    load_chunk(STAGE);
    int c = 0;
#pragma unroll 1
    for (; c + 3 <= NC; c += 3) {
        step(c,     0,         2 * STAGE);
        step(c + 1, STAGE,     0);
        step(c + 2, 2 * STAGE, STAGE);
    }
    if (c < NC) { step(c, 0, 2 * STAGE); c++; }
    if (c < NC) { step(c, STAGE, 0); }

    // ---------------- epilogue ----------------
    if (P.mode == 0) {
        float* C = P.C + zq * P.Co + zr * P.Ci;
#pragma unroll
        for (int mi = 0; mi < 2; mi++) {
#pragma unroll
            for (int j = 0; j < 8; j++) {
                int rl  = wm * 32 + mi * 16 + gid;
                int col = wn * 64 + j * 8 + tig * 2;
                float2 v0 = make_float2(acc[mi][j][0] * P.alpha, acc[mi][j][1] * P.alpha);
                float2 v1 = make_float2(acc[mi][j][2] * P.alpha, acc[mi][j][3] * P.alpha);
                *(float2*)(C + (long long)(brow + rl) * P.ldc + bcol + col)     = v0;
                *(float2*)(C + (long long)(brow + rl + 8) * P.ldc + bcol + col) = v1;
            }
        }
    } else if (bcol < 1024) {
        // Q|K tile -> split halves into Ch/Cl (ldc = 1024)
#pragma unroll
        for (int mi = 0; mi < 2; mi++) {
#pragma unroll
            for (int j = 0; j < 8; j++) {
                int rl  = wm * 32 + mi * 16 + gid;
                int col = wn * 64 + j * 8 + tig * 2;
                float bx = P.bias[bcol + col], by = P.bias[bcol + col + 1];
#pragma unroll
                for (int h = 0; h < 2; h++) {
                    float v0 = acc[mi][j][2 * h + 0] + bx;
                    float v1 = acc[mi][j][2 * h + 1] + by;
                    __half h0 = __float2half_rn(v0), h1 = __float2half_rn(v1);
                    long long o = (long long)(brow + rl + 8 * h) * 1024 + bcol + col;
                    *(__half2*)(P.Ch + o) = __halves2half2(h0, h1);
                    *(__half2*)(P.Cl + o) = __halves2half2(
                        __float2half_rn(v0 - __half2float(h0)),
                        __float2half_rn(v1 - __half2float(h1)));
                }
            }
        }
    } else {
        // V tile: bias-add, transpose via f32 smem staging, split into vth/vtl
        float* stg = (float*)smem;          // [128][129] = 66048B
        __syncthreads();
#pragma unroll
        for (int mi = 0; mi < 2; mi++) {
#pragma unroll
            for (int j = 0; j < 8; j++) {
                int rl  = wm * 32 + mi * 16 + gid;
                int col = wn * 64 + j * 8 + tig * 2;
                float bx = P.bias[bcol + col], by = P.bias[bcol + col + 1];
                stg[rl * 129 + col]           = acc[mi][j][0] + bx;
                stg[rl * 129 + col + 1]       = acc[mi][j][1] + by;
                stg[(rl + 8) * 129 + col]     = acc[mi][j][2] + bx;
                stg[(rl + 8) * 129 + col + 1] = acc[mi][j][3] + by;
            }
        }
        __syncthreads();
        const int z2 = brow >> 8;
        const int t0 = brow & 255;
        long long base = (long long)z2 * 131072 + (long long)(bcol - 1024) * 256 + t0;
        for (int idx = tid; idx < 16384; idx += 256) {
            int l = idx >> 7, m = idx & 127;
            float v = stg[m * 129 + l];
            __half h = __float2half_rn(v);
            long long o = base + (long long)l * 256 + m;
            P.vth[o] = h;
            P.vtl[o] = __float2half_rn(v - __half2float(h));
        }
    }
}

// ---------------------------------------------------------------------------
__global__ void split_kernel(const float* __restrict__ src,
                             __half* __restrict__ hi, __half* __restrict__ lo,
                             int n4)
{
    int i = blockIdx.x * blockDim.x + threadIdx.x;
    if (i >= n4) return;
    float4 v = ((const float4*)src)[i];
    __half h0 = __float2half_rn(v.x), h1 = __float2half_rn(v.y);
    __half h2 = __float2half_rn(v.z), h3 = __float2half_rn(v.w);
    ((__half2*)hi)[2 * i]     = __halves2half2(h0, h1);
    ((__half2*)hi)[2 * i + 1] = __halves2half2(h2, h3);
    ((__half2*)lo)[2 * i]     = __halves2half2(
        __float2half_rn(v.x - __half2float(h0)),
        __float2half_rn(v.y - __half2float(h1)));
    ((__half2*)lo)[2 * i + 1] = __halves2half2(
        __float2half_rn(v.z - __half2float(h2)),
        __float2half_rn(v.w - __half2float(h3)));
}

// ---------------------------------------------------------------------------
// Zero out_mat EXCEPT the diagonal blocks (those are fully written by the
// scores GEMM + softmax; writes are address-disjoint so this can run
// concurrently with the whole pipeline).
__global__ void fill_offdiag_kernel(float4* __restrict__ p)
{
    long long i = (long long)blockIdx.x * blockDim.x + threadIdx.x;
    const long long stride = (long long)gridDim.x * blockDim.x;
    const float4 z = make_float4(0.f, 0.f, 0.f, 0.f);
    for (; i < 16777216LL; i += stride) {
        int col4 = (int)(i & 511);
        int d    = (int)((i >> 17) & 7);            // (row >> 8) & 7, row = i >> 9
        if ((col4 >> 6) != d) p[i] = z;
    }
}

// ---------------------------------------------------------------------------
__global__ __launch_bounds__(256) void softmax_mask_kernel(
    float* __restrict__ out_mat, const int* __restrict__ n_ptr,
    __half* __restrict__ ah, __half* __restrict__ al)
{
    const int gwarp = ((blockIdx.x * blockDim.x) + threadIdx.x) >> 5;
    const int lane  = threadIdx.x & 31;
    const int s  = gwarp & 255;
    const int bd = gwarp >> 8;
    const int d  = bd & 7;
    const int b  = bd >> 3;

    float* row = out_mat + ((long long)(b * 2048 + d * 256 + s)) * 2048 + d * 256;
    long long abase = (long long)bd * 65536 + (long long)s * 256;

    float vals[8];
    float maxv = -INFINITY;
#pragma unroll
    for (int i = 0; i < 8; i++) {
        vals[i] = row[lane + i * 32];
        maxv = fmaxf(maxv, vals[i]);
    }
#pragma unroll
    for (int off = 16; off; off >>= 1)
        maxv = fmaxf(maxv, __shfl_xor_sync(0xFFFFFFFFu, maxv, off));

    float sum = 0.0f;
#pragma unroll
    for (int i = 0; i < 8; i++) { vals[i] = __expf(vals[i] - maxv); sum += vals[i]; }
#pragma unroll
    for (int off = 16; off; off >>= 1)
        sum += __shfl_xor_sync(0xFFFFFFFFu, sum, off);

    const float inv = 1.0f / sum;
    const int n = *n_ptr;
#pragma unroll
    for (int i = 0; i < 8; i++) {
        int t  = lane + i * 32;
        int ds = abs(t - s);
        bool masked = (ds == 0) || (ds >= 1 && (long long)ds * n <= 256);
        float v = masked ? 0.0f : vals[i] * inv;
        row[t] = v;
        __half h = __float2half_rn(v);
        ah[abase + t] = h;
        al[abase + t] = __float2half_rn(v - __half2float(h));
    }
}

// ---------------------------------------------------------------------------
extern "C" void kernel_launch(void* const* d_in, const int* in_sizes, int n_in,
                              void* d_out, int out_size)
{
    const float* x  = (const float*)d_in[0];
    const float* W  = (const float*)d_in[1];
    const float* bq = (const float*)d_in[2];
    const int* n_p  = (const int*)d_in[3];

    float* out     = (float*)d_out;
    float* out_mat = out + 16777216LL;

    __half *xs0, *xs1, *ws0, *ws1, *qk0, *qk1, *vt0, *vt1, *as0, *as1;
    cudaGetSymbolAddress((void**)&xs0, g_xs);  xs1 = xs0 + 16777216;
    cudaGetSymbolAddress((void**)&ws0, g_ws);  ws1 = ws0 + 786432;
    cudaGetSymbolAddress((void**)&qk0, g_qks); qk1 = qk0 + 33554432;
    cudaGetSymbolAddress((void**)&vt0, g_vts); vt1 = vt0 + 16777216;
    cudaGetSymbolAddress((void**)&as0, g_as);  as1 = as0 + 8388608;

    cudaFuncSetAttribute(gemm_tc<3>, cudaFuncAttributeMaxDynamicSharedMemorySize, SMEM_BYTES);
    cudaFuncSetAttribute(gemm_tc<2>, cudaFuncAttributeMaxDynamicSharedMemorySize, SMEM_BYTES);

    // one-time low-priority side-stream + events (created on the uncaptured
    // correctness call; reused identically on every capture)
    static cudaStream_t s1 = nullptr;
    static cudaEvent_t evFork = nullptr, evJoin = nullptr;
    if (!s1) {
        int prLo = 0, prHi = 0;
        cudaDeviceGetStreamPriorityRange(&prLo, &prHi);   // prLo = least urgent
        cudaStreamCreateWithPriority(&s1, cudaStreamNonBlocking, prLo);
        cudaEventCreateWithFlags(&evFork, cudaEventDisableTiming);
        cudaEventCreateWithFlags(&evJoin, cudaEventDisableTiming);
    }

    // ---- fork: off-diagonal zero-fill on low-priority s1 (disjoint writes;
    // joined only at the end — soaks idle-SM windows of the pipeline)
    cudaEventRecord(evFork, 0);
    cudaStreamWaitEvent(s1, evFork, 0);
    fill_offdiag_kernel<<<8192, 256, 0, s1>>>((float4*)out_mat);
    cudaEventRecord(evJoin, s1);

    // 0) split x and W into half planes (main stream)
    split_kernel<<<16384, 256>>>(x, xs0, xs1, 4194304);
    split_kernel<<<768, 256>>>(W, ws0, ws1, 196608);

    // 2) QKV: Q|K -> g_qks split, V -> g_vts split transposed
    {
        GP P = {};
        P.Ah = xs0; P.Al = xs1; P.lda = 512;  P.Ao = 0; P.Ai = 0;
        P.Bh = ws0; P.Bl = ws1; P.ldb = 512;  P.Bo = 0; P.Bi = 0;
        P.Ch = qk0; P.Cl = qk1;
        P.vth = vt0; P.vtl = vt1;
        P.bias = bq; P.alpha = 1.0f; P.K = 512; P.mode = 1;
        gemm_tc<3><<<dim3(12, 256, 1), 256, SMEM_BYTES>>>(P);
    }

    // 3) scores = Q K^T / sqrt(512) -> diagonal blocks of out_mat (f32)
    {
        GP P = {};
        P.Ah = qk0;       P.Al = qk1;       P.lda = 1024; P.Ao = 8LL * 262144; P.Ai = 262144;
        P.Bh = qk0 + 512; P.Bl = qk1 + 512; P.ldb = 1024; P.Bo = 8LL * 262144; P.Bi = 262144;
        P.C = out_mat; P.ldc = 2048; P.Co = 4194304; P.Ci = 524544;
        P.alpha = 0.044194173824159216f; P.K = 512; P.mode = 0;
        gemm_tc<3><<<dim3(2, 2, 128), 256, SMEM_BYTES>>>(P);
    }

    // 4) softmax + mask; writes f32 attn + split-half attn
    softmax_mask_kernel<<<4096, 256>>>(out_mat, n_p, as0, as1);

    // 5) out = attn * V — 2-term split (attn in [0,1]; dropped lo_attn*V term
    //    contributes ~5e-4 global rel err, well under the 1e-3 gate)
    {
        GP P = {};
        P.Ah = as0; P.Al = as1; P.lda = 256; P.Ao = 8LL * 65536;  P.Ai = 65536;
        P.Bh = vt0; P.Bl = vt1; P.ldb = 256; P.Bo = 8LL * 131072; P.Bi = 131072;
        P.C = out; P.ldc = 512; P.Co = 1048576; P.Ci = 131072;
        P.alpha = 1.0f; P.K = 256; P.mode = 0;
        gemm_tc<2><<<dim3(4, 2, 128), 256, SMEM_BYTES>>>(P);
    }

    // ---- join: fill must complete before the launch's work is "done" ----
    cudaStreamWaitEvent(0, evJoin, 0);
}

// round 17
// speedup vs baseline: 1.3207x; 1.2405x over previous
#include <cuda_runtime.h>
#include <cuda_fp16.h>
#include <stdint.h>
#include <math.h>

// ---------------------------------------------------------------------------
// B=16, D=8, S=256, L=512.
//   x [32768,512] f32 | Wqkv [1536,512] | bqkv [1536] | n (int)
// d_out: output [16,2048,512] (16,777,216 f32) then out_mat [16,2048,2048].
//
// All GEMMs: legacy mma.sync.m16n8k16 fp16 split precision, 2-term
// (hi*hi + hi*lo) everywhere: per-GEMM contribution ~1.4-2e-4 global rel
// err (R16 measured 1.9e-4 for AV alone); RSS total ~3.2e-4 < 1e-3 gate.
// R13 pipeline structure: monolithic QKV, off-diag fill on low-priority
// stream joined at end. 3-stage cp.async ring, XOR-swizzled smem, ldmatrix.
// ---------------------------------------------------------------------------

static __device__ __half g_xs [2][16777216];  // x split planes [32768*512]
static __device__ __half g_ws [2][786432];    // Wqkv split planes [1536*512]
static __device__ __half g_qks[2][33554432];  // Q|K split [32768*1024]
static __device__ __half g_vts[2][16777216];  // V^T split [128 z][512 l][256 t]
static __device__ __half g_as [2][8388608];   // attn split [128 z][256 s][256 t]

// smem: 3 stages x 4 planes; plane = 128 rows x 64B (XOR swizzled) = 8192B
#define PLANE 8192
#define STAGE 32768
#define SMEM_BYTES 98304

#define MMA_F16(d, a0, a1, a2, a3, b0, b1)                                     \
    asm volatile(                                                              \
        "mma.sync.aligned.m16n8k16.row.col.f32.f16.f16.f32 "                   \
        "{%0,%1,%2,%3},{%4,%5,%6,%7},{%8,%9},{%0,%1,%2,%3};"                   \
        : "+f"((d)[0]), "+f"((d)[1]), "+f"((d)[2]), "+f"((d)[3])               \
        : "r"(a0), "r"(a1), "r"(a2), "r"(a3), "r"(b0), "r"(b1))

#define LDSM4(r, addr)                                                         \
    asm volatile("ldmatrix.sync.aligned.m8n8.x4.shared.b16 {%0,%1,%2,%3}, [%4];" \
                 : "=r"((r)[0]), "=r"((r)[1]), "=r"((r)[2]), "=r"((r)[3])      \
                 : "r"(addr))

#define CP16(dst, src)                                                         \
    asm volatile("cp.async.cg.shared.global [%0], [%1], 16;"                   \
                 :: "r"(dst), "l"(src))
#define CP_COMMIT() asm volatile("cp.async.commit_group;" ::: "memory")
#define CP_WAIT(n)  asm volatile("cp.async.wait_group %0;" :: "n"(n) : "memory")

__device__ __forceinline__ uint32_t smem_u32(const void* p) {
    uint32_t a;
    asm("{ .reg .u64 t; cvta.to.shared.u64 t, %1; cvt.u32.u64 %0, t; }" : "=r"(a) : "l"(p));
    return a;
}

// swizzled byte offset of 16B-unit u in row r (64B rows)
__device__ __forceinline__ uint32_t swz(int r, int u) {
    return (uint32_t)(r * 64 + ((u ^ ((r >> 1) & 3)) << 4));
}

struct GP {
    const __half *Ah, *Al; int lda; long long Ao, Ai;
    const __half *Bh, *Bl; int ldb; long long Bo, Bi;
    float* C; int ldc; long long Co, Ci;        // mode 0 output
    __half *Ch, *Cl;                            // mode 1: Q|K split output
    __half *vth, *vtl;                          // mode 1: V^T split output
    const float* bias;
    float alpha;
    int K;
    int mode;     // 0 = f32 C; 1 = QKV (split C; bcol>=1024 -> vt transposed)
};

// ---------------------------------------------------------------------------
template <int TERMS>
__global__ __launch_bounds__(256, 2) void gemm_tc(GP P)
{
    extern __shared__ char smem[];
    const uint32_t sb = smem_u32(smem);

    const int tid = threadIdx.x, lane = tid & 31, wid = tid >> 5;
    const int gid = lane >> 2, tig = lane & 3;
    const int wm = wid & 3, wn = wid >> 2;
    const int lrow = lane & 15;
    const int lu   = lane >> 4;

    const long long zq = blockIdx.z >> 3, zr = blockIdx.z & 7;
    const int brow = blockIdx.y * 128, bcol = blockIdx.x * 128;

    // ---- running cp.async source pointers (advance +32 halves per chunk) ----
    const int cr = tid >> 2, cu = tid & 3;
    const uint32_t csw = swz(cr, cu);                 // swz(cr+64,cu) = csw+4096
    const __half* pAh0 = P.Ah + zq * P.Ao + zr * P.Ai +
                         (long long)(brow + cr) * P.lda + cu * 8;
    const __half* pAl0 = P.Al + zq * P.Ao + zr * P.Ai +
                         (long long)(brow + cr) * P.lda + cu * 8;
    const __half* pBh0 = P.Bh + zq * P.Bo + zr * P.Bi +
                         (long long)(bcol + cr) * P.ldb + cu * 8;
    const __half* pBl0 = P.Bl + zq * P.Bo + zr * P.Bi +
                         (long long)(bcol + cr) * P.ldb + cu * 8;
    const __half* pAh1 = pAh0 + (long long)64 * P.lda;
    const __half* pAl1 = pAl0 + (long long)64 * P.lda;
    const __half* pBh1 = pBh0 + (long long)64 * P.ldb;
    const __half* pBl1 = pBl0 + (long long)64 * P.ldb;

    float acc[2][8][4];
#pragma unroll
    for (int i = 0; i < 2; i++)
#pragma unroll
        for (int j = 0; j < 8; j++)
#pragma unroll
            for (int q = 0; q < 4; q++) acc[i][j][q] = 0.0f;

    const int NC = P.K >> 5;

    auto load_chunk = [&](uint32_t stByte) {
        const uint32_t base = sb + stByte;
        uint32_t d0 = base + csw, d1 = base + csw + 4096;
        CP16(d0,             pAh0);
        CP16(d0 + PLANE,     pAl0);
        CP16(d0 + 2 * PLANE, pBh0);
        CP16(d0 + 3 * PLANE, pBl0);
        CP16(d1,             pAh1);
        CP16(d1 + PLANE,     pAl1);
        CP16(d1 + 2 * PLANE, pBh1);
        CP16(d1 + 3 * PLANE, pBl1);
        CP_COMMIT();
        pAh0 += 32; pAl0 += 32; pBh0 += 32; pBl0 += 32;
        pAh1 += 32; pAl1 += 32; pBh1 += 32; pBl1 += 32;
    };

    // ---- precomputed LDSM offsets (swizzle linear in 16-row steps) ----
    const int ar0 = wm * 32 + lrow;
    const int br0 = wn * 64 + lrow;
    const uint32_t aoff0 = swz(ar0, lu),     aoff1 = swz(ar0, 2 + lu);
    const uint32_t boff0 = swz(br0, lu) + 2 * PLANE;
    const uint32_t boff1 = swz(br0, 2 + lu) + 2 * PLANE;

    // one k16 step: LDSM fragments + TERMS*32 HMMAs (term-major)
    auto compute_ks = [&](uint32_t base, int ks) {
        const uint32_t ab = base + (ks ? aoff1 : aoff0);
        const uint32_t bb = base + (ks ? boff1 : boff0);
        uint32_t aH[2][4], aL[2][4];
#pragma unroll
        for (int mi = 0; mi < 2; mi++) {
            uint32_t ad = ab + mi * 1024;
            LDSM4(aH[mi], ad);
            if (TERMS == 3) LDSM4(aL[mi], ad + PLANE);
        }
#pragma unroll
        for (int jj = 0; jj < 4; jj++) {
            uint32_t bd = bb + jj * 1024;
            uint32_t bh[4], bl[4];
            LDSM4(bh, bd);
            LDSM4(bl, bd + PLANE);
#pragma unroll
            for (int e = 0; e < 2; e++)
#pragma unroll
                for (int mi = 0; mi < 2; mi++)
                    MMA_F16(acc[mi][jj * 2 + e],
                            aH[mi][0], aH[mi][1], aH[mi][2], aH[mi][3],
                            bh[e], bh[2 + e]);
#pragma unroll
            for (int e = 0; e < 2; e++)
#pragma unroll
                for (int mi = 0; mi < 2; mi++)
                    MMA_F16(acc[mi][jj * 2 + e],
                            aH[mi][0], aH[mi][1], aH[mi][2], aH[mi][3],
                            bl[e], bl[2 + e]);
            if (TERMS == 3) {
#pragma unroll
                for (int e = 0; e < 2; e++)
#pragma unroll
                    for (int mi = 0; mi < 2; mi++)
                        MMA_F16(acc[mi][jj * 2 + e],
                                aL[mi][0], aL[mi][1], aL[mi][2], aL[mi][3],
                                bh[e], bh[2 + e]);
            }
        }
    };

    // one pipeline step: barrier -> compute ks0 -> issue next load -> ks1
    auto step = [&](int c, uint32_t stByte, uint32_t ldByte) {
        CP_WAIT(1);
        __syncthreads();
        const uint32_t base = sb + stByte;
        compute_ks(base, 0);
        if (c + 2 < NC) load_chunk(ldByte);
        else            CP_COMMIT();
        compute_ks(base, 1);
    };

    // 3-stage ring, unrolled so stage offsets are compile-time constants
    load_chunk(0);
    load_chunk(STAGE);
    int c = 0;
#pragma unroll 1
    for (; c + 3 <= NC; c += 3) {
        step(c,     0,         2 * STAGE);
        step(c + 1, STAGE,     0);
        step(c + 2, 2 * STAGE, STAGE);
    }
    if (c < NC) { step(c, 0, 2 * STAGE); c++; }
    if (c < NC) { step(c, STAGE, 0); }

    // ---------------- epilogue ----------------
    if (P.mode == 0) {
        float* C = P.C + zq * P.Co + zr * P.Ci;
#pragma unroll
        for (int mi = 0; mi < 2; mi++) {
#pragma unroll
            for (int j = 0; j < 8; j++) {
                int rl  = wm * 32 + mi * 16 + gid;
                int col = wn * 64 + j * 8 + tig * 2;
                float2 v0 = make_float2(acc[mi][j][0] * P.alpha, acc[mi][j][1] * P.alpha);
                float2 v1 = make_float2(acc[mi][j][2] * P.alpha, acc[mi][j][3] * P.alpha);
                *(float2*)(C + (long long)(brow + rl) * P.ldc + bcol + col)     = v0;
                *(float2*)(C + (long long)(brow + rl + 8) * P.ldc + bcol + col) = v1;
            }
        }
    } else if (bcol < 1024) {
        // Q|K tile -> split halves into Ch/Cl (ldc = 1024)
#pragma unroll
        for (int mi = 0; mi < 2; mi++) {
#pragma unroll
            for (int j = 0; j < 8; j++) {
                int rl  = wm * 32 + mi * 16 + gid;
                int col = wn * 64 + j * 8 + tig * 2;
                float bx = P.bias[bcol + col], by = P.bias[bcol + col + 1];
#pragma unroll
                for (int h = 0; h < 2; h++) {
                    float v0 = acc[mi][j][2 * h + 0] + bx;
                    float v1 = acc[mi][j][2 * h + 1] + by;
                    __half h0 = __float2half_rn(v0), h1 = __float2half_rn(v1);
                    long long o = (long long)(brow + rl + 8 * h) * 1024 + bcol + col;
                    *(__half2*)(P.Ch + o) = __halves2half2(h0, h1);
                    *(__half2*)(P.Cl + o) = __halves2half2(
                        __float2half_rn(v0 - __half2float(h0)),
                        __float2half_rn(v1 - __half2float(h1)));
                }
            }
        }
    } else {
        // V tile: bias-add, transpose via f32 smem staging, split into vth/vtl
        float* stg = (float*)smem;          // [128][129] = 66048B
        __syncthreads();
#pragma unroll
        for (int mi = 0; mi < 2; mi++) {
#pragma unroll
            for (int j = 0; j < 8; j++) {
                int rl  = wm * 32 + mi * 16 + gid;
                int col = wn * 64 + j * 8 + tig * 2;
                float bx = P.bias[bcol + col], by = P.bias[bcol + col + 1];
                stg[rl * 129 + col]           = acc[mi][j][0] + bx;
                stg[rl * 129 + col + 1]       = acc[mi][j][1] + by;
                stg[(rl + 8) * 129 + col]     = acc[mi][j][2] + bx;
                stg[(rl + 8) * 129 + col + 1] = acc[mi][j][3] + by;
            }
        }
        __syncthreads();
        const int z2 = brow >> 8;
        const int t0 = brow & 255;
        long long base = (long long)z2 * 131072 + (long long)(bcol - 1024) * 256 + t0;
        for (int idx = tid; idx < 16384; idx += 256) {
            int l = idx >> 7, m = idx & 127;
            float v = stg[m * 129 + l];
            __half h = __float2half_rn(v);
            long long o = base + (long long)l * 256 + m;
            P.vth[o] = h;
            P.vtl[o] = __float2half_rn(v - __half2float(h));
        }
    }
}

// ---------------------------------------------------------------------------
__global__ void split_kernel(const float* __restrict__ src,
                             __half* __restrict__ hi, __half* __restrict__ lo,
                             int n4)
{
    int i = blockIdx.x * blockDim.x + threadIdx.x;
    if (i >= n4) return;
    float4 v = ((const float4*)src)[i];
    __half h0 = __float2half_rn(v.x), h1 = __float2half_rn(v.y);
    __half h2 = __float2half_rn(v.z), h3 = __float2half_rn(v.w);
    ((__half2*)hi)[2 * i]     = __halves2half2(h0, h1);
    ((__half2*)hi)[2 * i + 1] = __halves2half2(h2, h3);
    ((__half2*)lo)[2 * i]     = __halves2half2(
        __float2half_rn(v.x - __half2float(h0)),
        __float2half_rn(v.y - __half2float(h1)));
    ((__half2*)lo)[2 * i + 1] = __halves2half2(
        __float2half_rn(v.z - __half2float(h2)),
        __float2half_rn(v.w - __half2float(h3)));
}

// ---------------------------------------------------------------------------
// Zero out_mat EXCEPT the diagonal blocks (those are fully written by the
// scores GEMM + softmax; writes are address-disjoint so this can run
// concurrently with the whole pipeline).
__global__ void fill_offdiag_kernel(float4* __restrict__ p)
{
    long long i = (long long)blockIdx.x * blockDim.x + threadIdx.x;
    const long long stride = (long long)gridDim.x * blockDim.x;
    const float4 z = make_float4(0.f, 0.f, 0.f, 0.f);
    for (; i < 16777216LL; i += stride) {
        int col4 = (int)(i & 511);
        int d    = (int)((i >> 17) & 7);            // (row >> 8) & 7, row = i >> 9
        if ((col4 >> 6) != d) p[i] = z;
    }
}

// ---------------------------------------------------------------------------
__global__ __launch_bounds__(256) void softmax_mask_kernel(
    float* __restrict__ out_mat, const int* __restrict__ n_ptr,
    __half* __restrict__ ah, __half* __restrict__ al)
{
    const int gwarp = ((blockIdx.x * blockDim.x) + threadIdx.x) >> 5;
    const int lane  = threadIdx.x & 31;
    const int s  = gwarp & 255;
    const int bd = gwarp >> 8;
    const int d  = bd & 7;
    const int b  = bd >> 3;

    float* row = out_mat + ((long long)(b * 2048 + d * 256 + s)) * 2048 + d * 256;
    long long abase = (long long)bd * 65536 + (long long)s * 256;

    float vals[8];
    float maxv = -INFINITY;
#pragma unroll
    for (int i = 0; i < 8; i++) {
        vals[i] = row[lane + i * 32];
        maxv = fmaxf(maxv, vals[i]);
    }
#pragma unroll
    for (int off = 16; off; off >>= 1)
        maxv = fmaxf(maxv, __shfl_xor_sync(0xFFFFFFFFu, maxv, off));

    float sum = 0.0f;
#pragma unroll
    for (int i = 0; i < 8; i++) { vals[i] = __expf(vals[i] - maxv); sum += vals[i]; }
#pragma unroll
    for (int off = 16; off; off >>= 1)
        sum += __shfl_xor_sync(0xFFFFFFFFu, sum, off);

    const float inv = 1.0f / sum;
    const int n = *n_ptr;
#pragma unroll
    for (int i = 0; i < 8; i++) {
        int t  = lane + i * 32;
        int ds = abs(t - s);
        bool masked = (ds == 0) || (ds >= 1 && (long long)ds * n <= 256);
        float v = masked ? 0.0f : vals[i] * inv;
        row[t] = v;
        __half h = __float2half_rn(v);
        ah[abase + t] = h;
        al[abase + t] = __float2half_rn(v - __half2float(h));
    }
}

// ---------------------------------------------------------------------------
extern "C" void kernel_launch(void* const* d_in, const int* in_sizes, int n_in,
                              void* d_out, int out_size)
{
    const float* x  = (const float*)d_in[0];
    const float* W  = (const float*)d_in[1];
    const float* bq = (const float*)d_in[2];
    const int* n_p  = (const int*)d_in[3];

    float* out     = (float*)d_out;
    float* out_mat = out + 16777216LL;

    __half *xs0, *xs1, *ws0, *ws1, *qk0, *qk1, *vt0, *vt1, *as0, *as1;
    cudaGetSymbolAddress((void**)&xs0, g_xs);  xs1 = xs0 + 16777216;
    cudaGetSymbolAddress((void**)&ws0, g_ws);  ws1 = ws0 + 786432;
    cudaGetSymbolAddress((void**)&qk0, g_qks); qk1 = qk0 + 33554432;
    cudaGetSymbolAddress((void**)&vt0, g_vts); vt1 = vt0 + 16777216;
    cudaGetSymbolAddress((void**)&as0, g_as);  as1 = as0 + 8388608;

    cudaFuncSetAttribute(gemm_tc<2>, cudaFuncAttributeMaxDynamicSharedMemorySize, SMEM_BYTES);

    // one-time low-priority side-stream + events (created on the uncaptured
    // correctness call; reused identically on every capture)
    static cudaStream_t s1 = nullptr;
    static cudaEvent_t evFork = nullptr, evJoin = nullptr;
    if (!s1) {
        int prLo = 0, prHi = 0;
        cudaDeviceGetStreamPriorityRange(&prLo, &prHi);   // prLo = least urgent
        cudaStreamCreateWithPriority(&s1, cudaStreamNonBlocking, prLo);
        cudaEventCreateWithFlags(&evFork, cudaEventDisableTiming);
        cudaEventCreateWithFlags(&evJoin, cudaEventDisableTiming);
    }

    // ---- fork: off-diagonal zero-fill on low-priority s1 (disjoint writes;
    // joined only at the end — soaks idle-SM windows of the pipeline)
    cudaEventRecord(evFork, 0);
    cudaStreamWaitEvent(s1, evFork, 0);
    fill_offdiag_kernel<<<8192, 256, 0, s1>>>((float4*)out_mat);
    cudaEventRecord(evJoin, s1);

    // 0) split x and W into half planes (main stream)
    split_kernel<<<16384, 256>>>(x, xs0, xs1, 4194304);
    split_kernel<<<768, 256>>>(W, ws0, ws1, 196608);

    // 2) QKV (2-term): Q|K -> g_qks split, V -> g_vts split transposed
    {
        GP P = {};
        P.Ah = xs0; P.Al = xs1; P.lda = 512;  P.Ao = 0; P.Ai = 0;
        P.Bh = ws0; P.Bl = ws1; P.ldb = 512;  P.Bo = 0; P.Bi = 0;
        P.Ch = qk0; P.Cl = qk1;
        P.vth = vt0; P.vtl = vt1;
        P.bias = bq; P.alpha = 1.0f; P.K = 512; P.mode = 1;
        gemm_tc<2><<<dim3(12, 256, 1), 256, SMEM_BYTES>>>(P);
    }

    // 3) scores (2-term) = Q K^T / sqrt(512) -> diagonal blocks of out_mat
    {
        GP P = {};
        P.Ah = qk0;       P.Al = qk1;       P.lda = 1024; P.Ao = 8LL * 262144; P.Ai = 262144;
        P.Bh = qk0 + 512; P.Bl = qk1 + 512; P.ldb = 1024; P.Bo = 8LL * 262144; P.Bi = 262144;
        P.C = out_mat; P.ldc = 2048; P.Co = 4194304; P.Ci = 524544;
        P.alpha = 0.044194173824159216f; P.K = 512; P.mode = 0;
        gemm_tc<2><<<dim3(2, 2, 128), 256, SMEM_BYTES>>>(P);
    }

    // 4) softmax + mask; writes f32 attn + split-half attn
    softmax_mask_kernel<<<4096, 256>>>(out_mat, n_p, as0, as1);

    // 5) out = attn * V (2-term)
    {
        GP P = {};
        P.Ah = as0; P.Al = as1; P.lda = 256; P.Ao = 8LL * 65536;  P.Ai = 65536;
        P.Bh = vt0; P.Bl = vt1; P.ldb = 256; P.Bo = 8LL * 131072; P.Bi = 131072;
        P.C = out; P.ldc = 512; P.Co = 1048576; P.Ci = 131072;
        P.alpha = 1.0f; P.K = 256; P.mode = 0;
        gemm_tc<2><<<dim3(4, 2, 128), 256, SMEM_BYTES>>>(P);
    }

    // ---- join: fill must complete before the launch's work is "done" ----
    cudaStreamWaitEvent(0, evJoin, 0);
}